// round 3
// baseline (speedup 1.0000x reference)
#include <cuda_runtime.h>
#include <cstdint>
#include <math.h>

// Problem constants
#define TRI   32640      // 255 * 128, strict lower triangle count
#define NMAT  256
#define BATCH 1024
#define HIDW  1024
#define INW   256

// Device scratch (no allocations allowed): pre-rounded tf32 operands + hidden acts
__device__ float g_w2r[TRI * HIDW];    // 133.7 MB, first TRI rows of W2, tf32-rounded
__device__ float g_xr [BATCH * INW];   // x, tf32-rounded
__device__ float g_w1r[HIDW * INW];    // W1, tf32-rounded
__device__ float g_h  [BATCH * HIDW];  // softplus hidden, stored tf32-rounded

// ---------------- helpers ----------------
__device__ __forceinline__ uint32_t smem_u32(const void* p){
    uint32_t a;
    asm("{ .reg .u64 t; cvta.to.shared.u64 t, %1; cvt.u32.u64 %0, t; }" : "=r"(a) : "l"(p));
    return a;
}
__device__ __forceinline__ uint32_t f2tf(float f){
    uint32_t r; asm("cvt.rna.tf32.f32 %0, %1;" : "=r"(r) : "f"(f)); return r;
}
__device__ __forceinline__ void cp16(uint32_t s, const void* g){
    asm volatile("cp.async.cg.shared.global [%0], [%1], 16;" :: "r"(s), "l"(g) : "memory");
}
#define CP_COMMIT() asm volatile("cp.async.commit_group;" ::: "memory")
#define CP_WAIT1()  asm volatile("cp.async.wait_group 1;" ::: "memory")

// chunk permutation: conflict-free for LDS.128 consumers AND cp.async producers
__device__ __forceinline__ int cperm(int r){ return ((r & 1) << 2) | ((r >> 1) & 3); }

__device__ __forceinline__ uint4 lds128(uint32_t base, int row, int c){
    uint32_t addr = base + (uint32_t)(row * 128) + (uint32_t)((c ^ cperm(row)) << 4);
    uint4 v;
    asm volatile("ld.shared.v4.b32 {%0,%1,%2,%3}, [%4];"
                 : "=r"(v.x), "=r"(v.y), "=r"(v.z), "=r"(v.w) : "r"(addr));
    return v;
}
__device__ __forceinline__ void mma8(float* d, uint32_t a0, uint32_t a1, uint32_t a2, uint32_t a3,
                                     uint32_t b0, uint32_t b1){
    asm volatile(
        "mma.sync.aligned.m16n8k8.row.col.f32.tf32.tf32.f32 "
        "{%0,%1,%2,%3}, {%4,%5,%6,%7}, {%8,%9}, {%0,%1,%2,%3};"
        : "+f"(d[0]), "+f"(d[1]), "+f"(d[2]), "+f"(d[3])
        : "r"(a0), "r"(a1), "r"(a2), "r"(a3), "r"(b0), "r"(b1));
}

static constexpr int BM = 128, BN = 128, BK = 32, STAGES = 3;
static constexpr int STAGE_BYTES = (BM + BN) * BK * 4;          // 32 KB
static constexpr int SMEM_BYTES  = STAGES * STAGE_BYTES;        // 96 KB

// -------------------------------------------------------------------------
// Pre-round to tf32 (rna), vectorized. dst: 0 -> g_w2r, 1 -> g_xr, 2 -> g_w1r
// -------------------------------------------------------------------------
__global__ void __launch_bounds__(256) round_tf32_k(const float4* __restrict__ in, int n4, int dst)
{
    int i = blockIdx.x * 256 + threadIdx.x;
    if (i >= n4) return;
    float4 v = in[i];
    v.x = __uint_as_float(f2tf(v.x));
    v.y = __uint_as_float(f2tf(v.y));
    v.z = __uint_as_float(f2tf(v.z));
    v.w = __uint_as_float(f2tf(v.w));
    float4* out = (dst == 0) ? (float4*)g_w2r : (dst == 1) ? (float4*)g_xr : (float4*)g_w1r;
    out[i] = v;
}

// -------------------------------------------------------------------------
// Pipelined tf32 mma.sync GEMM: C[128x128] tile = A[m0:,:K] * B[n0:,:K]^T + bias
// Operands are pre-rounded tf32 (no cvt in mainloop). k-order inside each
// 32-wide tile is permuted (identically for A and B) so each thread's fragment
// data is a contiguous float4 -> LDS.128.
// mode 0: A=g_xr, B=g_w1r, O=g_h, epilogue softplus + tf32-round
// mode 1: A=g_h,  B=g_w2r, O=d_out, epilogue scatters to strict lower triangle
// -------------------------------------------------------------------------
__global__ void __launch_bounds__(256, 2)
gemm_tf32(const float* __restrict__ bias, float* __restrict__ O_, int K, int mode)
{
    extern __shared__ char smem[];
    const uint32_t sbase = smem_u32(smem);
    const int tid  = threadIdx.x;
    const int lane = tid & 31;
    const int wid  = tid >> 5;
    const int wm   = wid & 3;        // 4 warps along M (32 rows each)
    const int wn   = wid >> 2;       // 2 warps along N (64 cols each)
    const int m0   = blockIdx.x * BM;
    const int n0   = blockIdx.y * BN;
    const int t    = lane & 3;
    const int g    = lane >> 2;

    const float* A  = (mode == 1) ? (const float*)g_h  : (const float*)g_xr;
    const float* B_ = (mode == 1) ? (const float*)g_w2r : (const float*)g_w1r;
    float*       O  = (mode == 0) ? (float*)g_h : O_;

    const int KT = K >> 5;           // K-tiles of 32

    // ---- stage loader: 128x32 fp32 A and B tiles, 16B cp.async, permuted chunks ----
    auto load_stage = [&](int stage, int kt){
        const uint32_t sa = sbase + stage * STAGE_BYTES;
        const uint32_t sb = sa + BM * BK * 4;
        const float* Ag = A  + (size_t)m0 * K + kt * BK;
        const float* Bg = B_ + (size_t)n0 * K + kt * BK;
        #pragma unroll
        for (int it = 0; it < 4; it++){
            int idx = tid + it * 256;          // 1024 16B chunks per tile
            int row = idx >> 3, ch = idx & 7;
            uint32_t soff = (uint32_t)(row * 128 + ((ch ^ cperm(row)) << 4));
            cp16(sa + soff, Ag + (size_t)row * K + ch * 4);
            cp16(sb + soff, Bg + (size_t)row * K + ch * 4);
        }
    };

    float acc[2][8][4];
    #pragma unroll
    for (int mf = 0; mf < 2; mf++)
        #pragma unroll
        for (int nf = 0; nf < 8; nf++)
            #pragma unroll
            for (int q = 0; q < 4; q++) acc[mf][nf][q] = 0.0f;

    // prologue: 2 stages in flight
    load_stage(0, 0); CP_COMMIT();
    load_stage(1, 1); CP_COMMIT();

    for (int kt = 0; kt < KT; kt++){
        CP_WAIT1();
        __syncthreads();
        // prefetch stage kt+2 (stage (kt+2)%3 was consumed at iter kt-1; every
        // warp passed the barrier above after that compute)
        if (kt + 2 < KT) load_stage((kt + 2) % STAGES, kt + 2);
        CP_COMMIT();

        const uint32_t sa = sbase + (kt % STAGES) * STAGE_BYTES;
        const uint32_t sb = sa + BM * BK * 4;

        #pragma unroll
        for (int kq = 0; kq < 2; kq++){          // two 16-k groups per tile
            const int ca = kq * 4 + t;           // chunk holding this thread's 4 k's
            uint4 A0[2], A1[2];
            #pragma unroll
            for (int mf = 0; mf < 2; mf++){
                int r = wm * 32 + mf * 16 + g;
                A0[mf] = lds128(sa, r,     ca);
                A1[mf] = lds128(sa, r + 8, ca);
            }
            #pragma unroll
            for (int ng = 0; ng < 2; ng++){      // B in two groups of 4 (reg pressure)
                uint4 Bv[4];
                #pragma unroll
                for (int nf = 0; nf < 4; nf++){
                    int n = wn * 64 + (ng * 4 + nf) * 8 + g;
                    Bv[nf] = lds128(sb, n, ca);
                }
                #pragma unroll
                for (int mf = 0; mf < 2; mf++)
                    #pragma unroll
                    for (int nf = 0; nf < 4; nf++){
                        float* d = acc[mf][ng * 4 + nf];
                        // k-subset {.., 4t, 4t+1, ..}
                        mma8(d, A0[mf].x, A1[mf].x, A0[mf].y, A1[mf].y, Bv[nf].x, Bv[nf].y);
                        // k-subset {.., 4t+2, 4t+3, ..}
                        mma8(d, A0[mf].z, A1[mf].z, A0[mf].w, A1[mf].w, Bv[nf].z, Bv[nf].w);
                    }
            }
        }
    }

    // ---- epilogue (accumulators only; no barrier needed) ----
    #pragma unroll
    for (int mf = 0; mf < 2; mf++){
        const int rbase = m0 + wm * 32 + mf * 16 + g;
        #pragma unroll
        for (int nf = 0; nf < 8; nf++){
            const int e0 = n0 + wn * 64 + nf * 8 + t * 2;
            const float bv0 = bias[e0], bv1 = bias[e0 + 1];
            if (mode == 1){
                // e -> (i,j): i(i-1)/2 <= e < i(i+1)/2 ; j = e - i(i-1)/2
                int i = (int)((1.0f + sqrtf(8.0f * (float)e0 + 1.0f)) * 0.5f);
                while (i * (i - 1) / 2 > e0) i--;
                while ((i + 1) * i / 2 <= e0) i++;
                int j = e0 - i * (i - 1) / 2;
                int i1 = i, j1 = j + 1;
                if (j1 >= i1){ i1 = i + 1; j1 = 0; }
                float* o0 = O + (size_t)rbase * (NMAT * NMAT);
                float* o8 = o0 + (size_t)8 * (NMAT * NMAT);
                o0[i  * NMAT + j ] = acc[mf][nf][0] + bv0;
                o0[i1 * NMAT + j1] = acc[mf][nf][1] + bv1;
                o8[i  * NMAT + j ] = acc[mf][nf][2] + bv0;
                o8[i1 * NMAT + j1] = acc[mf][nf][3] + bv1;
            } else {
                float* o0 = O + (size_t)rbase * HIDW + e0;
                float* o8 = o0 + (size_t)8 * HIDW;
                #pragma unroll
                for (int q = 0; q < 4; q++){
                    float v = acc[mf][nf][q] + ((q & 1) ? bv1 : bv0);
                    float av = fabsf(v);
                    v = fmaxf(v, 0.0f) + log1pf(__expf(-av));   // softplus
                    // store tf32-rounded so GEMM2 needs no cvt
                    ((q & 2) ? o8 : o0)[q & 1] = __uint_as_float(f2tf(v));
                }
            }
        }
    }
}

// -------------------------------------------------------------------------
// Antisymmetrize: upper triangle = -lower^T, diagonal = 0. Tiled 32x32.
// blockIdx.x = batch, blockIdx.y = tile-pair index (ti >= tj), 36 pairs.
// -------------------------------------------------------------------------
__global__ void __launch_bounds__(256) antisym_kernel(float* __restrict__ out)
{
    __shared__ float s[32][33];
    const int b  = blockIdx.x;
    const int pr = blockIdx.y;
    int ti = 0;
    while ((ti + 1) * (ti + 2) / 2 <= pr) ti++;
    const int tj = pr - ti * (ti + 1) / 2;
    const int tx = threadIdx.x & 31, ty = threadIdx.x >> 5;  // 32 x 8
    float* base = out + (size_t)b * (NMAT * NMAT);

    #pragma unroll
    for (int yy = 0; yy < 4; yy++){
        int r = ty + yy * 8;
        s[r][tx] = base[(size_t)(ti * 32 + r) * NMAT + tj * 32 + tx];
    }
    __syncthreads();
    if (ti != tj){
        #pragma unroll
        for (int yy = 0; yy < 4; yy++){
            int r = ty + yy * 8;
            base[(size_t)(tj * 32 + r) * NMAT + ti * 32 + tx] = -s[tx][r];
        }
    } else {
        #pragma unroll
        for (int yy = 0; yy < 4; yy++){
            int r = ty + yy * 8;
            if (tx > r)
                base[(size_t)(ti * 32 + r) * NMAT + ti * 32 + tx] = -s[tx][r];
            else if (tx == r)
                base[(size_t)(ti * 32 + r) * NMAT + ti * 32 + tx] = 0.0f;
        }
    }
}

// -------------------------------------------------------------------------
extern "C" void kernel_launch(void* const* d_in, const int* in_sizes, int n_in,
                              void* d_out, int out_size)
{
    const float* x  = (const float*)d_in[0];   // [1024, 256]
    const float* W1 = (const float*)d_in[1];   // [1024, 256]
    const float* b1 = (const float*)d_in[2];   // [1024]
    const float* W2 = (const float*)d_in[3];   // [32896, 1024]
    const float* b2 = (const float*)d_in[4];   // [32896]
    float* out = (float*)d_out;                // [1024, 256, 256]

    cudaFuncSetAttribute(gemm_tf32, cudaFuncAttributeMaxDynamicSharedMemorySize, SMEM_BYTES);

    // Pre-round operands to tf32 (rna) into device scratch
    round_tf32_k<<<(TRI * HIDW / 4 + 255) / 256, 256>>>((const float4*)W2, TRI * HIDW / 4, 0);
    round_tf32_k<<<(BATCH * INW / 4 + 255) / 256, 256>>>((const float4*)x,  BATCH * INW / 4, 1);
    round_tf32_k<<<(HIDW * INW / 4 + 255) / 256, 256>>>((const float4*)W1, HIDW * INW / 4, 2);

    // GEMM1: h = softplus(x @ W1^T + b1) -> g_h   (M=1024, N=1024, K=256)
    gemm_tf32<<<dim3(8, 8), 256, SMEM_BYTES>>>(b1, nullptr, 256, 0);
    // GEMM2: elements = h @ W2^T + b2, scattered into strict lower triangle
    //        (M=1024, N=TRI=255*128, K=1024). x-fastest => 8 CTAs share a W2 tile.
    gemm_tf32<<<dim3(8, 255), 256, SMEM_BYTES>>>(b2, out, 1024, 1);
    // Upper triangle = -lower^T, diagonal = 0
    antisym_kernel<<<dim3(1024, 36), 256>>>(out);
}

// round 4
// speedup vs baseline: 1.4653x; 1.4653x over previous
#include <cuda_runtime.h>
#include <cuda_fp16.h>
#include <cstdint>
#include <math.h>

// Problem constants
#define TRI   32640      // 255 * 128, strict lower triangle count
#define NMAT  256
#define BATCH 1024
#define HIDW  1024
#define INW   256

// Device scratch (no allocations allowed): fp16 operands + hidden acts
__device__ __half g_w2h[TRI * HIDW];    // 66.8 MB, first TRI rows of W2 in fp16
__device__ __half g_xh [BATCH * INW];
__device__ __half g_w1h[HIDW * INW];
__device__ __half g_h  [BATCH * HIDW]; // softplus hidden, fp16

// ---------------- helpers ----------------
__device__ __forceinline__ uint32_t smem_u32(const void* p){
    uint32_t a;
    asm("{ .reg .u64 t; cvta.to.shared.u64 t, %1; cvt.u32.u64 %0, t; }" : "=r"(a) : "l"(p));
    return a;
}
__device__ __forceinline__ void cp16(uint32_t s, const void* g){
    asm volatile("cp.async.cg.shared.global [%0], [%1], 16;" :: "r"(s), "l"(g) : "memory");
}
#define CP_COMMIT() asm volatile("cp.async.commit_group;" ::: "memory")
#define CP_WAIT1()  asm volatile("cp.async.wait_group 1;" ::: "memory")

__device__ __forceinline__ uint4 lds128(uint32_t base, int row, int t){
    uint32_t addr = base + (uint32_t)(row * 64 + t * 16);   // 64B rows, conflict-free
    uint4 v;
    asm volatile("ld.shared.v4.b32 {%0,%1,%2,%3}, [%4];"
                 : "=r"(v.x), "=r"(v.y), "=r"(v.z), "=r"(v.w) : "r"(addr));
    return v;
}
// fp16 MMA, fp32 accumulate. Logical k-order permuted (same perm on A and B).
__device__ __forceinline__ void mma16(float* d, uint32_t a0, uint32_t a1, uint32_t a2, uint32_t a3,
                                      uint32_t b0, uint32_t b1){
    asm volatile(
        "mma.sync.aligned.m16n8k16.row.col.f32.f16.f16.f32 "
        "{%0,%1,%2,%3}, {%4,%5,%6,%7}, {%8,%9}, {%0,%1,%2,%3};"
        : "+f"(d[0]), "+f"(d[1]), "+f"(d[2]), "+f"(d[3])
        : "r"(a0), "r"(a1), "r"(a2), "r"(a3), "r"(b0), "r"(b1));
}

static constexpr int BM = 128, BN = 128, BK = 32, STAGES = 3;
static constexpr int STAGE_BYTES = (BM + BN) * BK * 2;          // 16 KB
static constexpr int SMEM_BYTES  = STAGES * STAGE_BYTES;        // 48 KB

// -------------------------------------------------------------------------
// fp32 -> fp16 conversion. dst: 0 -> g_w2h, 1 -> g_xh, 2 -> g_w1h
// -------------------------------------------------------------------------
__global__ void __launch_bounds__(256) conv_half_k(const float4* __restrict__ in, int n4, int dst)
{
    int i = blockIdx.x * 256 + threadIdx.x;
    if (i >= n4) return;
    float4 v = in[i];
    __half2 h0 = __floats2half2_rn(v.x, v.y);
    __half2 h1 = __floats2half2_rn(v.z, v.w);
    uint2 w;
    w.x = *(uint32_t*)&h0;
    w.y = *(uint32_t*)&h1;
    __half* out = (dst == 0) ? g_w2h : (dst == 1) ? g_xh : g_w1h;
    ((uint2*)out)[i] = w;
}

// -------------------------------------------------------------------------
// Pipelined fp16 mma.sync GEMM: C[128x128] tile = A[m0:,:K] * B[n0:,:K]^T + bias
// mode 0: A=g_xh, B=g_w1h, O=g_h (fp16), epilogue softplus
// mode 1: A=g_h,  B=g_w2h, O=d_out (fp32), scatter to strict lower triangle
// -------------------------------------------------------------------------
__global__ void __launch_bounds__(256, 2)
gemm_f16(const float* __restrict__ bias, float* __restrict__ O_, int K, int mode)
{
    extern __shared__ char smem[];
    const uint32_t sbase = smem_u32(smem);
    const int tid  = threadIdx.x;
    const int lane = tid & 31;
    const int wid  = tid >> 5;
    const int wm   = wid & 3;        // 4 warps along M (32 rows each)
    const int wn   = wid >> 2;       // 2 warps along N (64 cols each)
    const int m0   = blockIdx.x * BM;
    const int n0   = blockIdx.y * BN;
    const int t    = lane & 3;
    const int g    = lane >> 2;

    const __half* A  = (mode == 1) ? g_h   : g_xh;
    const __half* B_ = (mode == 1) ? g_w2h : g_w1h;

    const int KT = K >> 5;           // K-tiles of 32

    // ---- stage loader: 128x32 fp16 A and B tiles (8KB each), 16B cp.async ----
    auto load_stage = [&](int stage, int kt){
        const uint32_t sa = sbase + stage * STAGE_BYTES;
        const uint32_t sb = sa + BM * BK * 2;
        const __half* Ag = A  + (size_t)m0 * K + kt * BK;
        const __half* Bg = B_ + (size_t)n0 * K + kt * BK;
        #pragma unroll
        for (int it = 0; it < 2; it++){
            int idx = tid + it * 256;          // 512 16B chunks per tile
            int row = idx >> 2, ch = idx & 3;
            uint32_t soff = (uint32_t)(row * 64 + ch * 16);
            cp16(sa + soff, Ag + (size_t)row * K + ch * 8);
            cp16(sb + soff, Bg + (size_t)row * K + ch * 8);
        }
    };

    float acc[2][8][4];
    #pragma unroll
    for (int mf = 0; mf < 2; mf++)
        #pragma unroll
        for (int nf = 0; nf < 8; nf++)
            #pragma unroll
            for (int q = 0; q < 4; q++) acc[mf][nf][q] = 0.0f;

    // prologue: 2 stages in flight
    load_stage(0, 0); CP_COMMIT();
    load_stage(1, 1); CP_COMMIT();

    for (int kt = 0; kt < KT; kt++){
        CP_WAIT1();
        __syncthreads();
        if (kt + 2 < KT) load_stage((kt + 2) % STAGES, kt + 2);
        CP_COMMIT();

        const uint32_t sa = sbase + (kt % STAGES) * STAGE_BYTES;
        const uint32_t sb = sa + BM * BK * 2;

        // One LDS.128 per row fetches phys k [8t..8t+7]: regs .x/.y feed MMA0
        // (k16 #0), .z/.w feed MMA1 (k16 #1); identical k-perm on A and B.
        uint4 a_lo[2], a_hi[2];
        #pragma unroll
        for (int mf = 0; mf < 2; mf++){
            int r = wm * 32 + mf * 16 + g;
            a_lo[mf] = lds128(sa, r,     t);
            a_hi[mf] = lds128(sa, r + 8, t);
        }
        #pragma unroll
        for (int ng = 0; ng < 2; ng++){
            uint4 Bv[4];
            #pragma unroll
            for (int nf = 0; nf < 4; nf++){
                int n = wn * 64 + (ng * 4 + nf) * 8 + g;
                Bv[nf] = lds128(sb, n, t);
            }
            #pragma unroll
            for (int mf = 0; mf < 2; mf++)
                #pragma unroll
                for (int nf = 0; nf < 4; nf++){
                    float* d = acc[mf][ng * 4 + nf];
                    mma16(d, a_lo[mf].x, a_hi[mf].x, a_lo[mf].y, a_hi[mf].y, Bv[nf].x, Bv[nf].y);
                    mma16(d, a_lo[mf].z, a_hi[mf].z, a_lo[mf].w, a_hi[mf].w, Bv[nf].z, Bv[nf].w);
                }
        }
    }

    // ---- epilogue ----
    #pragma unroll
    for (int mf = 0; mf < 2; mf++){
        const int rbase = m0 + wm * 32 + mf * 16 + g;
        #pragma unroll
        for (int nf = 0; nf < 8; nf++){
            const int e0 = n0 + wn * 64 + nf * 8 + t * 2;
            const float bv0 = bias[e0], bv1 = bias[e0 + 1];
            if (mode == 1){
                // e -> (i,j): i(i-1)/2 <= e < i(i+1)/2 ; j = e - i(i-1)/2
                int i = (int)((1.0f + sqrtf(8.0f * (float)e0 + 1.0f)) * 0.5f);
                while (i * (i - 1) / 2 > e0) i--;
                while ((i + 1) * i / 2 <= e0) i++;
                int j = e0 - i * (i - 1) / 2;
                int i1 = i, j1 = j + 1;
                if (j1 >= i1){ i1 = i + 1; j1 = 0; }
                float* o0 = O_ + (size_t)rbase * (NMAT * NMAT);
                float* o8 = o0 + (size_t)8 * (NMAT * NMAT);
                o0[i  * NMAT + j ] = acc[mf][nf][0] + bv0;
                o0[i1 * NMAT + j1] = acc[mf][nf][1] + bv1;
                o8[i  * NMAT + j ] = acc[mf][nf][2] + bv0;
                o8[i1 * NMAT + j1] = acc[mf][nf][3] + bv1;
            } else {
                __half* o0 = g_h + (size_t)rbase * HIDW + e0;
                __half* o8 = o0 + (size_t)8 * HIDW;
                float v0 = acc[mf][nf][0] + bv0, v1 = acc[mf][nf][1] + bv1;
                float v2 = acc[mf][nf][2] + bv0, v3 = acc[mf][nf][3] + bv1;
                // softplus
                v0 = fmaxf(v0, 0.0f) + log1pf(__expf(-fabsf(v0)));
                v1 = fmaxf(v1, 0.0f) + log1pf(__expf(-fabsf(v1)));
                v2 = fmaxf(v2, 0.0f) + log1pf(__expf(-fabsf(v2)));
                v3 = fmaxf(v3, 0.0f) + log1pf(__expf(-fabsf(v3)));
                *(__half2*)o0 = __floats2half2_rn(v0, v1);
                *(__half2*)o8 = __floats2half2_rn(v2, v3);
            }
        }
    }
}

// -------------------------------------------------------------------------
// Antisymmetrize: upper triangle = -lower^T, diagonal = 0. Tiled 32x32.
// -------------------------------------------------------------------------
__global__ void __launch_bounds__(256) antisym_kernel(float* __restrict__ out)
{
    __shared__ float s[32][33];
    const int b  = blockIdx.x;
    const int pr = blockIdx.y;
    int ti = 0;
    while ((ti + 1) * (ti + 2) / 2 <= pr) ti++;
    const int tj = pr - ti * (ti + 1) / 2;
    const int tx = threadIdx.x & 31, ty = threadIdx.x >> 5;  // 32 x 8
    float* base = out + (size_t)b * (NMAT * NMAT);

    #pragma unroll
    for (int yy = 0; yy < 4; yy++){
        int r = ty + yy * 8;
        s[r][tx] = base[(size_t)(ti * 32 + r) * NMAT + tj * 32 + tx];
    }
    __syncthreads();
    if (ti != tj){
        #pragma unroll
        for (int yy = 0; yy < 4; yy++){
            int r = ty + yy * 8;
            base[(size_t)(tj * 32 + r) * NMAT + ti * 32 + tx] = -s[tx][r];
        }
    } else {
        #pragma unroll
        for (int yy = 0; yy < 4; yy++){
            int r = ty + yy * 8;
            if (tx > r)
                base[(size_t)(ti * 32 + r) * NMAT + ti * 32 + tx] = -s[tx][r];
            else if (tx == r)
                base[(size_t)(ti * 32 + r) * NMAT + ti * 32 + tx] = 0.0f;
        }
    }
}

// -------------------------------------------------------------------------
extern "C" void kernel_launch(void* const* d_in, const int* in_sizes, int n_in,
                              void* d_out, int out_size)
{
    const float* x  = (const float*)d_in[0];   // [1024, 256]
    const float* W1 = (const float*)d_in[1];   // [1024, 256]
    const float* b1 = (const float*)d_in[2];   // [1024]
    const float* W2 = (const float*)d_in[3];   // [32896, 1024]
    const float* b2 = (const float*)d_in[4];   // [32896]
    float* out = (float*)d_out;                // [1024, 256, 256]

    cudaFuncSetAttribute(gemm_f16, cudaFuncAttributeMaxDynamicSharedMemorySize, SMEM_BYTES);

    // Convert operands to fp16 in device scratch
    conv_half_k<<<(TRI * HIDW / 4 + 255) / 256, 256>>>((const float4*)W2, TRI * HIDW / 4, 0);
    conv_half_k<<<(BATCH * INW / 4 + 255) / 256, 256>>>((const float4*)x,  BATCH * INW / 4, 1);
    conv_half_k<<<(HIDW * INW / 4 + 255) / 256, 256>>>((const float4*)W1, HIDW * INW / 4, 2);

    // GEMM1: h = softplus(x @ W1^T + b1) -> g_h (fp16)   (M=1024, N=1024, K=256)
    gemm_f16<<<dim3(8, 8), 256, SMEM_BYTES>>>(b1, nullptr, 256, 0);
    // GEMM2: elements = h @ W2^T + b2 -> strict lower triangle of out
    gemm_f16<<<dim3(8, 255), 256, SMEM_BYTES>>>(b2, out, 1024, 1);
    // Upper triangle = -lower^T, diagonal = 0
    antisym_kernel<<<dim3(1024, 36), 256>>>(out);
}